// round 9
// baseline (speedup 1.0000x reference)
#include <cuda_runtime.h>
#include <math.h>

// Problem dims (fixed)
#define BB 4
#define SS 1024
#define DM 512
#define HH 8
#define HDD 64
#define HIDD 2048
#define NT (BB*SS)                 // 4096 token rows
#define NDE ((size_t)NT*DM)        // 2097152
#define NHE ((size_t)NT*HIDD)      // 8388608
#define DDE ((size_t)DM*DM)        // 262144
#define GDE ((size_t)HIDD*DM)      // 1048576

typedef unsigned long long ull;
typedef unsigned int uint32;

// -------- scratch: one big __device__ array (no allocations allowed) --------
__device__ float g_scratch[96468992];

// ---- f32x2 packed helpers (FFMA2 path — attention kernels) ----
__device__ __forceinline__ ull pk2(float x) {
    ull r; asm("mov.b64 %0, {%1, %1};" : "=l"(r) : "f"(x)); return r;
}
__device__ __forceinline__ void fma2(ull &d, ull a, ull b) {
    asm("fma.rn.f32x2 %0, %1, %2, %0;" : "+l"(d) : "l"(a), "l"(b));
}
__device__ __forceinline__ float2 up2(ull v) {
    float2 f; asm("mov.b64 {%0, %1}, %2;" : "=f"(f.x), "=f"(f.y) : "l"(v)); return f;
}

// ---- tf32 helpers ----
__device__ __forceinline__ uint32 to_tf32(float x) {
    uint32 r; asm("cvt.rna.tf32.f32 %0, %1;" : "=r"(r) : "f"(x)); return r;
}
#define MMA_TF32(d, a, b) \
    asm volatile("mma.sync.aligned.m16n8k8.row.col.f32.tf32.tf32.f32 " \
                 "{%0,%1,%2,%3}, {%4,%5,%6,%7}, {%8,%9}, {%0,%1,%2,%3};" \
                 : "+f"(d[0]), "+f"(d[1]), "+f"(d[2]), "+f"(d[3]) \
                 : "r"(a[0]), "r"(a[1]), "r"(a[2]), "r"(a[3]), "r"(b[0]), "r"(b[1]))

// ---------------------------------------------------------------------------
__global__ __launch_bounds__(256) void make_w_kernel(const float* __restrict__ lm,
                                                     const float* __restrict__ ph,
                                                     float* __restrict__ wr,
                                                     float* __restrict__ wi, int n) {
    int i = blockIdx.x * 256 + threadIdx.x;
    if (i >= n) return;
    float m = expf(lm[i]);
    float p = ph[i];
    wr[i] = m * cosf(p);
    wi[i] = m * sinf(p);
}

// complex layernorm over last dim D=512; one block per row, 256 threads
__global__ __launch_bounds__(256) void cln_kernel(const float* __restrict__ xr,
                                                  const float* __restrict__ xi,
                                                  const float* __restrict__ gr,
                                                  const float* __restrict__ gi,
                                                  const float* __restrict__ br,
                                                  const float* __restrict__ bi,
                                                  float* __restrict__ outr,
                                                  float* __restrict__ outi) {
    int row = blockIdx.x;
    int t = threadIdx.x;
    const float* xrp = xr + (size_t)row * DM;
    const float* xip = xi + (size_t)row * DM;
    float a0 = xrp[t], a1 = xrp[t + 256];
    float b0 = xip[t], b1 = xip[t + 256];
    __shared__ float red[256];

    red[t] = a0 + a1; __syncthreads();
    for (int s2 = 128; s2 > 0; s2 >>= 1) { if (t < s2) red[t] += red[t + s2]; __syncthreads(); }
    float mr = red[0] * (1.0f / DM); __syncthreads();

    red[t] = b0 + b1; __syncthreads();
    for (int s2 = 128; s2 > 0; s2 >>= 1) { if (t < s2) red[t] += red[t + s2]; __syncthreads(); }
    float mi = red[0] * (1.0f / DM); __syncthreads();

    float c0 = a0 - mr, c1 = a1 - mr, d0 = b0 - mi, d1 = b1 - mi;
    red[t] = c0 * c0 + c1 * c1 + d0 * d0 + d1 * d1; __syncthreads();
    for (int s2 = 128; s2 > 0; s2 >>= 1) { if (t < s2) red[t] += red[t + s2]; __syncthreads(); }
    float inv = rsqrtf(red[0] * (1.0f / DM) + 1e-6f);

    float* orow = outr + (size_t)row * DM;
    float* oirow = outi + (size_t)row * DM;
    {
        float nr = c0 * inv, ni = d0 * inv;
        orow[t]  = nr * gr[t] - ni * gi[t] + br[t];
        oirow[t] = nr * gi[t] + ni * gr[t] + bi[t];
    }
    {
        int d_ = t + 256;
        float nr = c1 * inv, ni = d1 * inv;
        orow[d_]  = nr * gr[d_] - ni * gi[d_] + br[d_];
        oirow[d_] = nr * gi[d_] + ni * gr[d_] + bi[d_];
    }
}

// ============================================================================
// Tensor-core complex GEMM (tf32 mma.sync m16n8k8), 2-stage pipelined:
//   Cr = Ar@Wr^T - Ai@Wi^T + br ; Ci = Ar@Wi^T + Ai@Wr^T + bi
// A: (M,K) rm; W: (N,K) rm; C: (M,N) rm.
// Tiles: BM=128, BN=64, BK=16. 256 threads = 8 warps in 4(m) x 2(n) grid,
// each warp owns a 32x32 complex tile = (2 m16) x (4 n8) acc frags, R and I.
// Double SMEM buffer (dynamic, 61440B): tile i+1 is LDG'd into registers
// before computing tile i, then cvt+STS'd into the other buffer; single
// __syncthreads per iteration. tf32 rna conversion preserved at fill.
// SMEM row pad = 20 words -> fragment gather is conflict-free.
// ============================================================================
#define CG_BUFW 7680   // words per buffer: A 2*2560 + W 2*1280
#define CG_SMEM (2 * CG_BUFW * 4)

__global__ __launch_bounds__(256) void cgemm_tc_kernel(const float* __restrict__ Ar,
                                                       const float* __restrict__ Ai,
                                                       const float* __restrict__ Wr,
                                                       const float* __restrict__ Wi,
                                                       const float* __restrict__ bm,
                                                       const float* __restrict__ bp,
                                                       float* __restrict__ Cr,
                                                       float* __restrict__ Ci,
                                                       int M, int N, int K) {
    extern __shared__ uint32 smem[];

    int m0 = blockIdx.y * 128, n0 = blockIdx.x * 64;
    int tid = threadIdx.x;
    int warp = tid >> 5, lane = tid & 31;
    int wm = warp & 3, wn = warp >> 2;
    int g = lane >> 2, t = lane & 3;

    // fill coordinates (fixed): A rows rA0, rA0+64; W row rW; 4-col quads
    int rA0 = tid >> 2, c4 = (tid & 3) * 4;
    const float* gAr0 = Ar + (size_t)(m0 + rA0) * K + c4;
    const float* gAr1 = Ar + (size_t)(m0 + rA0 + 64) * K + c4;
    const float* gAi0 = Ai + (size_t)(m0 + rA0) * K + c4;
    const float* gAi1 = Ai + (size_t)(m0 + rA0 + 64) * K + c4;
    const float* gWr  = Wr + (size_t)(n0 + rA0) * K + c4;
    const float* gWi  = Wi + (size_t)(n0 + rA0) * K + c4;

    float4 pAr0, pAr1, pAi0, pAi1, pWr, pWi;

#define CG_LDG(k0) { \
    pAr0 = *(const float4*)(gAr0 + (k0)); \
    pAr1 = *(const float4*)(gAr1 + (k0)); \
    pAi0 = *(const float4*)(gAi0 + (k0)); \
    pAi1 = *(const float4*)(gAi1 + (k0)); \
    pWr  = *(const float4*)(gWr  + (k0)); \
    pWi  = *(const float4*)(gWi  + (k0)); }

#define CG_ST4(p, v) { (p)[0] = to_tf32((v).x); (p)[1] = to_tf32((v).y); \
                       (p)[2] = to_tf32((v).z); (p)[3] = to_tf32((v).w); }

#define CG_STS(buf) { uint32* b_ = (buf); \
    CG_ST4(b_ + rA0 * 20 + c4, pAr0); \
    CG_ST4(b_ + (rA0 + 64) * 20 + c4, pAr1); \
    CG_ST4(b_ + 2560 + rA0 * 20 + c4, pAi0); \
    CG_ST4(b_ + 2560 + (rA0 + 64) * 20 + c4, pAi1); \
    CG_ST4(b_ + 5120 + rA0 * 20 + c4, pWr); \
    CG_ST4(b_ + 6400 + rA0 * 20 + c4, pWi); }

    float accR[2][4][4], accI[2][4][4];
    #pragma unroll
    for (int mi = 0; mi < 2; mi++)
        #pragma unroll
        for (int ni = 0; ni < 4; ni++)
            #pragma unroll
            for (int e = 0; e < 4; e++) { accR[mi][ni][e] = 0.f; accI[mi][ni][e] = 0.f; }

    int nk = K >> 4;
    CG_LDG(0);
    CG_STS(smem);
    __syncthreads();
    CG_LDG(16);   // nk >= 2 always here (K >= 512)

    for (int i = 0; i < nk; i++) {
        const uint32* cur = smem + (i & 1) * CG_BUFW;
        const uint32* cAr = cur;
        const uint32* cAi = cur + 2560;
        const uint32* cWr = cur + 5120;
        const uint32* cWi = cur + 6400;

        #pragma unroll
        for (int kk = 0; kk < 16; kk += 8) {
            uint32 fwr[4][2], fwi[4][2];
            #pragma unroll
            for (int ni = 0; ni < 4; ni++) {
                int n = (wn * 32 + ni * 8 + g) * 20 + kk + t;
                fwr[ni][0] = cWr[n]; fwr[ni][1] = cWr[n + 4];
                fwi[ni][0] = cWi[n]; fwi[ni][1] = cWi[n + 4];
            }
            #pragma unroll
            for (int mi = 0; mi < 2; mi++) {
                int r = (wm * 32 + mi * 16 + g) * 20 + kk + t;
                int r8 = r + 160;
                uint32 fa[4]  = {cAr[r], cAr[r8], cAr[r + 4], cAr[r8 + 4]};
                uint32 fb[4]  = {cAi[r], cAi[r8], cAi[r + 4], cAi[r8 + 4]};
                uint32 fbn[4] = {fb[0] ^ 0x80000000u, fb[1] ^ 0x80000000u,
                                 fb[2] ^ 0x80000000u, fb[3] ^ 0x80000000u};
                #pragma unroll
                for (int ni = 0; ni < 4; ni++) {
                    MMA_TF32(accR[mi][ni], fa,  fwr[ni]);
                    MMA_TF32(accR[mi][ni], fbn, fwi[ni]);
                    MMA_TF32(accI[mi][ni], fa,  fwi[ni]);
                    MMA_TF32(accI[mi][ni], fb,  fwr[ni]);
                }
            }
        }

        if (i + 1 < nk) {
            uint32* nxt = smem + ((i + 1) & 1) * CG_BUFW;
            CG_STS(nxt);
            if (i + 2 < nk) CG_LDG((i + 2) << 4);
            __syncthreads();
        }
    }

    // epilogue: acc frag element (e0,e1)=row g, cols 2t,2t+1 ; (e2,e3)=row g+8
    #pragma unroll
    for (int ni = 0; ni < 4; ni++) {
        int n = n0 + wn * 32 + ni * 8 + 2 * t;
        float br0 = 0.f, br1 = 0.f, bi0 = 0.f, bi1 = 0.f;
        if (bm) {
            br0 = bm[n] * cosf(bp[n]);     bi0 = bm[n] * sinf(bp[n]);
            br1 = bm[n + 1] * cosf(bp[n + 1]); bi1 = bm[n + 1] * sinf(bp[n + 1]);
        }
        #pragma unroll
        for (int mi = 0; mi < 2; mi++) {
            int r = m0 + wm * 32 + mi * 16 + g;
            float* c0 = accR[mi][ni];
            float* c1 = accI[mi][ni];
            *(float2*)&Cr[(size_t)r * N + n]        = make_float2(c0[0] + br0, c0[1] + br1);
            *(float2*)&Cr[(size_t)(r + 8) * N + n]  = make_float2(c0[2] + br0, c0[3] + br1);
            *(float2*)&Ci[(size_t)r * N + n]        = make_float2(c1[0] + bi0, c1[1] + bi1);
            *(float2*)&Ci[(size_t)(r + 8) * N + n]  = make_float2(c1[2] + bi0, c1[3] + bi1);
        }
    }
}

// RoPE in place on q,k (real & imag). Angles up to 1023 rad -> double sincos.
__global__ __launch_bounds__(256) void rope_kernel(float* __restrict__ qr, float* __restrict__ qi,
                                                   float* __restrict__ kr, float* __restrict__ ki) {
    int idx = blockIdx.x * 256 + threadIdx.x;   // < B*H*S*32 = 1048576
    int j = idx & 31;
    int s = (idx >> 5) & 1023;
    int h = (idx >> 15) & 7;
    int b = idx >> 18;
    double invf = pow(10000.0, -(double)(2 * j) / 64.0);
    double ang = (double)s * invf;
    double sd, cd;
    sincos(ang, &sd, &cd);
    float sn = (float)sd, cs = (float)cd;
    size_t base = (((size_t)b * SS + s) * DM) + h * HDD + j;
    float x0, x1;
    x0 = qr[base]; x1 = qr[base + 32]; qr[base] = x0 * cs - x1 * sn; qr[base + 32] = x1 * cs + x0 * sn;
    x0 = qi[base]; x1 = qi[base + 32]; qi[base] = x0 * cs - x1 * sn; qi[base + 32] = x1 * cs + x0 * sn;
    x0 = kr[base]; x1 = kr[base + 32]; kr[base] = x0 * cs - x1 * sn; kr[base + 32] = x1 * cs + x0 * sn;
    x0 = ki[base]; x1 = ki[base + 32]; ki[base] = x0 * cs - x1 * sn; ki[base + 32] = x1 * cs + x0 * sn;
}

// scores[bh, m, n] = (qr.kr + qi.ki)*scale ; only tiles with nt<=mt (causal)
__global__ __launch_bounds__(256) void scores_kernel(const float* __restrict__ qr,
                                                     const float* __restrict__ qi,
                                                     const float* __restrict__ kr,
                                                     const float* __restrict__ ki,
                                                     float* __restrict__ sc) {
    int bh = blockIdx.x, mt = blockIdx.y, nt = blockIdx.z;
    if (nt > mt) return;
    int b = bh >> 3, h = bh & 7;
    __shared__ float sQr[16][64], sQi[16][64], sKr[16][64], sKi[16][64];
    int m0 = mt * 64, n0 = nt * 64;
    int tx = threadIdx.x, ty = threadIdx.y;
    int tid = ty * 16 + tx;
    const size_t head_off = (size_t)b * SS * DM + (size_t)h * HDD;
    float acc[4][4] = {{0}};
    for (int k0 = 0; k0 < HDD; k0 += 16) {
        #pragma unroll
        for (int l = 0; l < 4; l++) {
            int idx = tid + l * 256;
            int r = idx >> 4, c = idx & 15;
            sQr[c][r] = qr[head_off + (size_t)(m0 + r) * DM + k0 + c];
            sQi[c][r] = qi[head_off + (size_t)(m0 + r) * DM + k0 + c];
            sKr[c][r] = kr[head_off + (size_t)(n0 + r) * DM + k0 + c];
            sKi[c][r] = ki[head_off + (size_t)(n0 + r) * DM + k0 + c];
        }
        __syncthreads();
        #pragma unroll
        for (int kk = 0; kk < 16; kk++) {
            float a[4], b2[4], c2[4], d2[4];
            #pragma unroll
            for (int j = 0; j < 4; j++) {
                a[j] = sQr[kk][ty * 4 + j];
                b2[j] = sQi[kk][ty * 4 + j];
                c2[j] = sKr[kk][tx * 4 + j];
                d2[j] = sKi[kk][tx * 4 + j];
            }
            #pragma unroll
            for (int i2 = 0; i2 < 4; i2++)
                #pragma unroll
                for (int j2 = 0; j2 < 4; j2++) {
                    acc[i2][j2] += a[i2] * c2[j2];
                    acc[i2][j2] += b2[i2] * d2[j2];
                }
        }
        __syncthreads();
    }
    const float scale = 0.125f;  // 1/sqrt(64)
    #pragma unroll
    for (int i2 = 0; i2 < 4; i2++) {
        size_t row = ((size_t)bh * SS + m0 + ty * 4 + i2) * SS;
        #pragma unroll
        for (int j2 = 0; j2 < 4; j2++)
            sc[row + n0 + tx * 4 + j2] = acc[i2][j2] * scale;
    }
}

// causal softmax per row; writes probs for col<=q, zeros for col>q
__global__ __launch_bounds__(256) void softmax_kernel(float* __restrict__ sc) {
    int row = blockIdx.x;          // bh*1024 + q
    int q = row & 1023;
    float* p = sc + (size_t)row * SS;
    int n = q + 1;
    int t = threadIdx.x;
    __shared__ float red[256];

    float mx = -1e30f;
    for (int i = t; i < n; i += 256) mx = fmaxf(mx, p[i]);
    red[t] = mx; __syncthreads();
    for (int s2 = 128; s2 > 0; s2 >>= 1) { if (t < s2) red[t] = fmaxf(red[t], red[t + s2]); __syncthreads(); }
    mx = red[0]; __syncthreads();

    float sum = 0.f;
    for (int i = t; i < n; i += 256) { float e = __expf(p[i] - mx); p[i] = e; sum += e; }
    red[t] = sum; __syncthreads();
    for (int s2 = 128; s2 > 0; s2 >>= 1) { if (t < s2) red[t] += red[t + s2]; __syncthreads(); }
    float inv = 1.0f / red[0];

    for (int i = t; i < n; i += 256) p[i] *= inv;
    for (int i = n + t; i < SS; i += 256) p[i] = 0.f;
}

// out[b, m, h*64+n] = sum_k attn[bh,m,k] * v[b,k,h*64+n]  (r and i), FFMA2
__global__ __launch_bounds__(256) void av_kernel(const float* __restrict__ attn,
                                                 const float* __restrict__ vr,
                                                 const float* __restrict__ vi,
                                                 float* __restrict__ ar_out,
                                                 float* __restrict__ ai_out) {
    int bh = blockIdx.x, mt = blockIdx.y;
    int b = bh >> 3, h = bh & 7;
    __shared__ float sP[16][64], sVr[16][64], sVi[16][64];
    int m0 = mt * 64;
    int tx = threadIdx.x, ty = threadIdx.y;
    int tid = ty * 16 + tx;
    ull accR[4][2], accI[4][2];
    #pragma unroll
    for (int i = 0; i < 4; i++) { accR[i][0] = accR[i][1] = 0ULL; accI[i][0] = accI[i][1] = 0ULL; }
    const size_t vbase = (size_t)b * SS * DM + (size_t)h * HDD;
    int kmax = m0 + 64;  // causal: tail zeros anyway
    for (int k0 = 0; k0 < kmax; k0 += 16) {
        #pragma unroll
        for (int l = 0; l < 4; l++) {
            int idx = tid + l * 256;
            int r = idx >> 4, c = idx & 15;
            sP[c][r] = attn[((size_t)bh * SS + m0 + r) * SS + k0 + c];
            int kk = idx >> 6, nn = idx & 63;
            sVr[kk][nn] = vr[vbase + (size_t)(k0 + kk) * DM + nn];
            sVi[kk][nn] = vi[vbase + (size_t)(k0 + kk) * DM + nn];
        }
        __syncthreads();
        #pragma unroll
        for (int kk = 0; kk < 16; kk++) {
            float4 pv = *(const float4*)&sP[kk][ty * 4];
            ulonglong2 vr2 = *(const ulonglong2*)&sVr[kk][tx * 4];
            ulonglong2 vi2 = *(const ulonglong2*)&sVi[kk][tx * 4];
            float ps[4] = {pv.x, pv.y, pv.z, pv.w};
            ull vrp[2] = {vr2.x, vr2.y};
            ull vip[2] = {vi2.x, vi2.y};
            #pragma unroll
            for (int i = 0; i < 4; i++) {
                ull pP = pk2(ps[i]);
                #pragma unroll
                for (int p = 0; p < 2; p++) {
                    fma2(accR[i][p], pP, vrp[p]);
                    fma2(accI[i][p], pP, vip[p]);
                }
            }
        }
        __syncthreads();
    }
    #pragma unroll
    for (int i = 0; i < 4; i++) {
        size_t orow = (size_t)b * SS * DM + (size_t)(m0 + ty * 4 + i) * DM + h * HDD + tx * 4;
        float2 r0 = up2(accR[i][0]), r1 = up2(accR[i][1]);
        float2 q0 = up2(accI[i][0]), q1 = up2(accI[i][1]);
        *(float4*)&ar_out[orow] = make_float4(r0.x, r0.y, r1.x, r1.y);
        *(float4*)&ai_out[orow] = make_float4(q0.x, q0.y, q1.x, q1.y);
    }
}

__global__ __launch_bounds__(256) void resid_kernel(const float* __restrict__ xr,
                                                    const float* __restrict__ xi,
                                                    const float* __restrict__ ar,
                                                    const float* __restrict__ ai,
                                                    float* __restrict__ out) {
    size_t i = (size_t)blockIdx.x * 256 + threadIdx.x;
    out[i] = xr[i] + ar[i];
    out[NDE + i] = xi[i] + ai[i];
}

__global__ __launch_bounds__(256) void gateact_kernel(float* __restrict__ gr, float* __restrict__ gi,
                                                      const float* __restrict__ ur,
                                                      const float* __restrict__ ui) {
    size_t i = (size_t)blockIdx.x * 256 + threadIdx.x;
    float a = gr[i], b = gi[i];
    float mag = sqrtf(a * a + b * b);
    float s = 1.0f / (1.0f + expf(-mag));
    float gar = a * s, gai = b * s;
    float u = ur[i], v = ui[i];
    gr[i] = gar * u - gai * v;
    gi[i] = gar * v + gai * u;
}

__global__ __launch_bounds__(256) void addout_kernel(const float* __restrict__ dr,
                                                     const float* __restrict__ di,
                                                     float* __restrict__ out) {
    size_t i = (size_t)blockIdx.x * 256 + threadIdx.x;
    out[i] += dr[i];
    out[NDE + i] += di[i];
}

// ---------------------------------------------------------------------------
extern "C" void kernel_launch(void* const* d_in, const int* in_sizes, int n_in,
                              void* d_out, int out_size) {
    const float* x_real = (const float*)d_in[0];
    const float* x_imag = (const float*)d_in[1];
    const float* ln1_gr = (const float*)d_in[2];
    const float* ln1_gi = (const float*)d_in[3];
    const float* ln1_br = (const float*)d_in[4];
    const float* ln1_bi = (const float*)d_in[5];
    const float* q_lm = (const float*)d_in[6];
    const float* q_ph = (const float*)d_in[7];
    const float* q_bm = (const float*)d_in[8];
    const float* q_bp = (const float*)d_in[9];
    const float* k_lm = (const float*)d_in[10];
    const float* k_ph = (const float*)d_in[11];
    const float* k_bm = (const float*)d_in[12];
    const float* k_bp = (const float*)d_in[13];
    const float* v_lm = (const float*)d_in[14];
    const float* v_ph = (const float*)d_in[15];
    const float* v_bm = (const float*)d_in[16];
    const float* v_bp = (const float*)d_in[17];
    const float* o_lm = (const float*)d_in[18];
    const float* o_ph = (const float*)d_in[19];
    const float* o_bm = (const float*)d_in[20];
    const float* o_bp = (const float*)d_in[21];
    const float* ln2_gr = (const float*)d_in[22];
    const float* ln2_gi = (const float*)d_in[23];
    const float* ln2_br = (const float*)d_in[24];
    const float* ln2_bi = (const float*)d_in[25];
    const float* gate_lm = (const float*)d_in[26];
    const float* gate_ph = (const float*)d_in[27];
    const float* up_lm = (const float*)d_in[28];
    const float* up_ph = (const float*)d_in[29];
    const float* down_lm = (const float*)d_in[30];
    const float* down_ph = (const float*)d_in[31];
    float* out = (float*)d_out;

    float* Sp = nullptr;
    cudaGetSymbolAddress((void**)&Sp, g_scratch);

    // allow 60KB dynamic smem for the pipelined GEMM (idempotent)
    cudaFuncSetAttribute(cgemm_tc_kernel,
                         cudaFuncAttributeMaxDynamicSharedMemorySize, CG_SMEM);

    // scratch layout
    float* qwr = Sp;            float* qwi = qwr + DDE;
    float* kwr = qwi + DDE;     float* kwi = kwr + DDE;
    float* vwr = kwi + DDE;     float* vwi = vwr + DDE;
    float* owr = vwi + DDE;     float* owi = owr + DDE;
    float* gwr = owi + DDE;     float* gwi = gwr + GDE;
    float* uwr = gwi + GDE;     float* uwi = uwr + GDE;
    float* dwr = uwi + GDE;     float* dwi = dwr + GDE;
    float* hr = dwi + GDE;      float* hi = hr + NDE;
    float* qr = hi + NDE;       float* qi = qr + NDE;
    float* kr = qi + NDE;       float* ki = kr + NDE;
    float* vr = ki + NDE;       float* vi = vr + NDE;
    float* ar = vi + NDE;       float* ai = ar + NDE;
    float* gr = ai + NDE;       float* gi = gr + NHE;
    float* ur = gi + NHE;       float* ui = ur + NHE;
    float* sc = ui + NHE;

    dim3 blk2(16, 16);

    // 1) materialize weights W = exp(lm) * e^{i ph}
    make_w_kernel<<<(int)(DDE / 256), 256>>>(q_lm, q_ph, qwr, qwi, (int)DDE);
    make_w_kernel<<<(int)(DDE / 256), 256>>>(k_lm, k_ph, kwr, kwi, (int)DDE);
    make_w_kernel<<<(int)(DDE / 256), 256>>>(v_lm, v_ph, vwr, vwi, (int)DDE);
    make_w_kernel<<<(int)(DDE / 256), 256>>>(o_lm, o_ph, owr, owi, (int)DDE);
    make_w_kernel<<<(int)(GDE / 256), 256>>>(gate_lm, gate_ph, gwr, gwi, (int)GDE);
    make_w_kernel<<<(int)(GDE / 256), 256>>>(up_lm, up_ph, uwr, uwi, (int)GDE);
    make_w_kernel<<<(int)(GDE / 256), 256>>>(down_lm, down_ph, dwr, dwi, (int)GDE);

    // 2) LN1
    cln_kernel<<<NT, 256>>>(x_real, x_imag, ln1_gr, ln1_gi, ln1_br, ln1_bi, hr, hi);

    // 3) QKV projections (tensor cores, tf32, pipelined)
    cgemm_tc_kernel<<<dim3(DM / 64, NT / 128), 256, CG_SMEM>>>(hr, hi, qwr, qwi, q_bm, q_bp, qr, qi, NT, DM, DM);
    cgemm_tc_kernel<<<dim3(DM / 64, NT / 128), 256, CG_SMEM>>>(hr, hi, kwr, kwi, k_bm, k_bp, kr, ki, NT, DM, DM);
    cgemm_tc_kernel<<<dim3(DM / 64, NT / 128), 256, CG_SMEM>>>(hr, hi, vwr, vwi, v_bm, v_bp, vr, vi, NT, DM, DM);

    // 4) RoPE on q,k
    rope_kernel<<<(BB * HH * SS * (HDD / 2)) / 256, 256>>>(qr, qi, kr, ki);

    // 5) attention (exact fp32 FFMA2)
    scores_kernel<<<dim3(BB * HH, SS / 64, SS / 64), blk2>>>(qr, qi, kr, ki, sc);
    softmax_kernel<<<BB * HH * SS, 256>>>(sc);
    av_kernel<<<dim3(BB * HH, SS / 64), blk2>>>(sc, vr, vi, ar, ai);

    // 6) output projection (reuse qr/qi as o-proj output)
    cgemm_tc_kernel<<<dim3(DM / 64, NT / 128), 256, CG_SMEM>>>(ar, ai, owr, owi, o_bm, o_bp, qr, qi, NT, DM, DM);

    // 7) residual -> d_out (res_r at [0..N), res_i at [N..2N))
    resid_kernel<<<(int)(NDE / 256), 256>>>(x_real, x_imag, qr, qi, out);

    // 8) LN2 (reads residual from d_out)
    cln_kernel<<<NT, 256>>>(out, out + NDE, ln2_gr, ln2_gi, ln2_br, ln2_bi, hr, hi);

    // 9) FFN (tensor cores, tf32, pipelined)
    cgemm_tc_kernel<<<dim3(HIDD / 64, NT / 128), 256, CG_SMEM>>>(hr, hi, gwr, gwi, nullptr, nullptr, gr, gi, NT, HIDD, DM);
    cgemm_tc_kernel<<<dim3(HIDD / 64, NT / 128), 256, CG_SMEM>>>(hr, hi, uwr, uwi, nullptr, nullptr, ur, ui, NT, HIDD, DM);
    gateact_kernel<<<(int)(NHE / 256), 256>>>(gr, gi, ur, ui);
    // down proj (reuse kr/ki as output)
    cgemm_tc_kernel<<<dim3(DM / 64, NT / 128), 256, CG_SMEM>>>(gr, gi, dwr, dwi, nullptr, nullptr, kr, ki, NT, DM, HIDD);

    // 10) final residual add into d_out
    addout_kernel<<<(int)(NDE / 256), 256>>>(kr, ki, out);
}

// round 10
// speedup vs baseline: 1.1504x; 1.1504x over previous
#include <cuda_runtime.h>
#include <math.h>

// Problem dims (fixed)
#define BB 4
#define SS 1024
#define DM 512
#define HH 8
#define HDD 64
#define HIDD 2048
#define NT (BB*SS)                 // 4096 token rows
#define NDE ((size_t)NT*DM)        // 2097152
#define NHE ((size_t)NT*HIDD)      // 8388608
#define DDE ((size_t)DM*DM)        // 262144
#define GDE ((size_t)HIDD*DM)      // 1048576

typedef unsigned long long ull;
typedef unsigned int uint32;

// -------- scratch: one big __device__ array (no allocations allowed) --------
__device__ float g_scratch[96468992];

// ---- f32x2 packed helpers (FFMA2 path — attention kernels) ----
__device__ __forceinline__ ull pk2(float x) {
    ull r; asm("mov.b64 %0, {%1, %1};" : "=l"(r) : "f"(x)); return r;
}
__device__ __forceinline__ void fma2(ull &d, ull a, ull b) {
    asm("fma.rn.f32x2 %0, %1, %2, %0;" : "+l"(d) : "l"(a), "l"(b));
}
__device__ __forceinline__ float2 up2(ull v) {
    float2 f; asm("mov.b64 {%0, %1}, %2;" : "=f"(f.x), "=f"(f.y) : "l"(v)); return f;
}

// ---- tf32 helpers ----
__device__ __forceinline__ uint32 to_tf32(float x) {
    uint32 r; asm("cvt.rna.tf32.f32 %0, %1;" : "=r"(r) : "f"(x)); return r;
}
#define MMA_TF32(d, a, b) \
    asm volatile("mma.sync.aligned.m16n8k8.row.col.f32.tf32.tf32.f32 " \
                 "{%0,%1,%2,%3}, {%4,%5,%6,%7}, {%8,%9}, {%0,%1,%2,%3};" \
                 : "+f"(d[0]), "+f"(d[1]), "+f"(d[2]), "+f"(d[3]) \
                 : "r"(a[0]), "r"(a[1]), "r"(a[2]), "r"(a[3]), "r"(b[0]), "r"(b[1]))

// ---------------------------------------------------------------------------
// all 7 magnitude/phase weight materializations in ONE launch
__global__ __launch_bounds__(256) void make_w_all_kernel(float* __restrict__ Sp,
    const float* __restrict__ q_lm, const float* __restrict__ q_ph,
    const float* __restrict__ k_lm, const float* __restrict__ k_ph,
    const float* __restrict__ v_lm, const float* __restrict__ v_ph,
    const float* __restrict__ o_lm, const float* __restrict__ o_ph,
    const float* __restrict__ g_lm, const float* __restrict__ g_ph,
    const float* __restrict__ u_lm, const float* __restrict__ u_ph,
    const float* __restrict__ d_lm, const float* __restrict__ d_ph) {
    int i = blockIdx.x * 256 + threadIdx.x;     // < 4*DDE + 3*GDE = 4194304
    const float *lm, *ph;
    float *wr, *wi;
    int off;
    if (i < (int)(4 * DDE)) {
        int w = i / (int)DDE; off = i - w * (int)DDE;
        lm = (w == 0) ? q_lm : (w == 1) ? k_lm : (w == 2) ? v_lm : o_lm;
        ph = (w == 0) ? q_ph : (w == 1) ? k_ph : (w == 2) ? v_ph : o_ph;
        wr = Sp + (size_t)w * 2 * DDE + off; wi = wr + DDE;
    } else {
        int j = i - (int)(4 * DDE);
        int w = j / (int)GDE; off = j - w * (int)GDE;
        lm = (w == 0) ? g_lm : (w == 1) ? u_lm : d_lm;
        ph = (w == 0) ? g_ph : (w == 1) ? u_ph : d_ph;
        wr = Sp + 8 * DDE + (size_t)w * 2 * GDE + off; wi = wr + GDE;
    }
    float m = expf(lm[off]);
    float p = ph[off];
    *wr = m * cosf(p);
    *wi = m * sinf(p);
}

// complex layernorm over last dim D=512; one block per row, 256 threads
__global__ __launch_bounds__(256) void cln_kernel(const float* __restrict__ xr,
                                                  const float* __restrict__ xi,
                                                  const float* __restrict__ gr,
                                                  const float* __restrict__ gi,
                                                  const float* __restrict__ br,
                                                  const float* __restrict__ bi,
                                                  float* __restrict__ outr,
                                                  float* __restrict__ outi) {
    int row = blockIdx.x;
    int t = threadIdx.x;
    const float* xrp = xr + (size_t)row * DM;
    const float* xip = xi + (size_t)row * DM;
    float a0 = xrp[t], a1 = xrp[t + 256];
    float b0 = xip[t], b1 = xip[t + 256];
    __shared__ float red[256];

    red[t] = a0 + a1; __syncthreads();
    for (int s2 = 128; s2 > 0; s2 >>= 1) { if (t < s2) red[t] += red[t + s2]; __syncthreads(); }
    float mr = red[0] * (1.0f / DM); __syncthreads();

    red[t] = b0 + b1; __syncthreads();
    for (int s2 = 128; s2 > 0; s2 >>= 1) { if (t < s2) red[t] += red[t + s2]; __syncthreads(); }
    float mi = red[0] * (1.0f / DM); __syncthreads();

    float c0 = a0 - mr, c1 = a1 - mr, d0 = b0 - mi, d1 = b1 - mi;
    red[t] = c0 * c0 + c1 * c1 + d0 * d0 + d1 * d1; __syncthreads();
    for (int s2 = 128; s2 > 0; s2 >>= 1) { if (t < s2) red[t] += red[t + s2]; __syncthreads(); }
    float inv = rsqrtf(red[0] * (1.0f / DM) + 1e-6f);

    float* orow = outr + (size_t)row * DM;
    float* oirow = outi + (size_t)row * DM;
    {
        float nr = c0 * inv, ni = d0 * inv;
        orow[t]  = nr * gr[t] - ni * gi[t] + br[t];
        oirow[t] = nr * gi[t] + ni * gr[t] + bi[t];
    }
    {
        int d_ = t + 256;
        float nr = c1 * inv, ni = d1 * inv;
        orow[d_]  = nr * gr[d_] - ni * gi[d_] + br[d_];
        oirow[d_] = nr * gi[d_] + ni * gr[d_] + bi[d_];
    }
}

// ============================================================================
// Tensor-core complex GEMM (tf32 mma.sync m16n8k8), batched over blockIdx.z:
//   Cr = Ar@Wr^T - Ai@Wi^T (+bias) ; Ci = Ar@Wi^T + Ai@Wr^T (+bias)
// Wr = Wbase + z*wzs, Wi = Wr + wioff ; Cr = Cbase + z*czs, Ci = Cr + cioff.
// mode 0: write acc+bias. mode 1: write acc+bias+X (fused residual, X=x_real/
// x_imag). mode 3: accumulate into C (fused final residual add).
// Tiles: BM=128, BN=64, BK=16. 256 threads = 8 warps (4m x 2n), each warp a
// 32x32 complex tile. Single SMEM buffer, 2 blocks/SM. Row pad 20 words.
// ============================================================================
__global__ __launch_bounds__(256, 2) void cgemm_tc_kernel(
    const float* __restrict__ Ar, const float* __restrict__ Ai,
    const float* __restrict__ Wbase, size_t wzs, size_t wioff,
    float* __restrict__ Cbase, size_t czs, size_t cioff,
    const float* __restrict__ bm0, const float* __restrict__ bp0,
    const float* __restrict__ bm1, const float* __restrict__ bp1,
    const float* __restrict__ bm2, const float* __restrict__ bp2,
    const float* __restrict__ Xr, const float* __restrict__ Xi,
    int mode, int M, int N, int K) {
    __shared__ uint32 sAr[128][20], sAi[128][20];
    __shared__ uint32 sWr[64][20],  sWi[64][20];

    int zz = blockIdx.z;
    const float* Wr = Wbase + (size_t)zz * wzs;
    const float* Wi = Wr + wioff;
    float* Cr = Cbase + (size_t)zz * czs;
    float* Ci = Cr + cioff;
    const float* bm = (zz == 0) ? bm0 : (zz == 1) ? bm1 : bm2;
    const float* bp = (zz == 0) ? bp0 : (zz == 1) ? bp1 : bp2;

    int m0 = blockIdx.y * 128, n0 = blockIdx.x * 64;
    int tid = threadIdx.x;
    int warp = tid >> 5, lane = tid & 31;
    int wm = warp & 3, wn = warp >> 2;
    int g = lane >> 2, t = lane & 3;

    float accR[2][4][4], accI[2][4][4];
    #pragma unroll
    for (int mi = 0; mi < 2; mi++)
        #pragma unroll
        for (int ni = 0; ni < 4; ni++)
            #pragma unroll
            for (int e = 0; e < 4; e++) { accR[mi][ni][e] = 0.f; accI[mi][ni][e] = 0.f; }

    for (int k0 = 0; k0 < K; k0 += 16) {
        // fill A tiles: 128x16 floats = 512 float4 per array; 2 per thread
        #pragma unroll
        for (int l = 0; l < 2; l++) {
            int idx = tid + l * 256;
            int r = idx >> 2, c4 = (idx & 3) * 4;
            float4 va = *(const float4*)&Ar[(size_t)(m0 + r) * K + k0 + c4];
            float4 vb = *(const float4*)&Ai[(size_t)(m0 + r) * K + k0 + c4];
            sAr[r][c4]     = to_tf32(va.x); sAr[r][c4 + 1] = to_tf32(va.y);
            sAr[r][c4 + 2] = to_tf32(va.z); sAr[r][c4 + 3] = to_tf32(va.w);
            sAi[r][c4]     = to_tf32(vb.x); sAi[r][c4 + 1] = to_tf32(vb.y);
            sAi[r][c4 + 2] = to_tf32(vb.z); sAi[r][c4 + 3] = to_tf32(vb.w);
        }
        // fill W tiles: 64x16 floats = 256 float4 per array; 1 per thread
        {
            int r = tid >> 2, c4 = (tid & 3) * 4;
            float4 va = *(const float4*)&Wr[(size_t)(n0 + r) * K + k0 + c4];
            float4 vb = *(const float4*)&Wi[(size_t)(n0 + r) * K + k0 + c4];
            sWr[r][c4]     = to_tf32(va.x); sWr[r][c4 + 1] = to_tf32(va.y);
            sWr[r][c4 + 2] = to_tf32(va.z); sWr[r][c4 + 3] = to_tf32(va.w);
            sWi[r][c4]     = to_tf32(vb.x); sWi[r][c4 + 1] = to_tf32(vb.y);
            sWi[r][c4 + 2] = to_tf32(vb.z); sWi[r][c4 + 3] = to_tf32(vb.w);
        }
        __syncthreads();

        #pragma unroll
        for (int kk = 0; kk < 16; kk += 8) {
            uint32 fwr[4][2], fwi[4][2];
            #pragma unroll
            for (int ni = 0; ni < 4; ni++) {
                int n = wn * 32 + ni * 8 + g;
                fwr[ni][0] = sWr[n][kk + t]; fwr[ni][1] = sWr[n][kk + t + 4];
                fwi[ni][0] = sWi[n][kk + t]; fwi[ni][1] = sWi[n][kk + t + 4];
            }
            #pragma unroll
            for (int mi = 0; mi < 2; mi++) {
                int r = wm * 32 + mi * 16 + g;
                uint32 fa[4]  = {sAr[r][kk + t], sAr[r + 8][kk + t],
                                 sAr[r][kk + t + 4], sAr[r + 8][kk + t + 4]};
                uint32 fb[4]  = {sAi[r][kk + t], sAi[r + 8][kk + t],
                                 sAi[r][kk + t + 4], sAi[r + 8][kk + t + 4]};
                uint32 fbn[4] = {fb[0] ^ 0x80000000u, fb[1] ^ 0x80000000u,
                                 fb[2] ^ 0x80000000u, fb[3] ^ 0x80000000u};
                #pragma unroll
                for (int ni = 0; ni < 4; ni++) {
                    MMA_TF32(accR[mi][ni], fa,  fwr[ni]);
                    MMA_TF32(accR[mi][ni], fbn, fwi[ni]);
                    MMA_TF32(accI[mi][ni], fa,  fwi[ni]);
                    MMA_TF32(accI[mi][ni], fb,  fwr[ni]);
                }
            }
        }
        __syncthreads();
    }

    // epilogue: acc frag element (e0,e1)=row g, cols 2t,2t+1 ; (e2,e3)=row g+8
    #pragma unroll
    for (int ni = 0; ni < 4; ni++) {
        int n = n0 + wn * 32 + ni * 8 + 2 * t;
        float br0 = 0.f, br1 = 0.f, bi0 = 0.f, bi1 = 0.f;
        if (bm) {
            br0 = bm[n] * cosf(bp[n]);         bi0 = bm[n] * sinf(bp[n]);
            br1 = bm[n + 1] * cosf(bp[n + 1]); bi1 = bm[n + 1] * sinf(bp[n + 1]);
        }
        #pragma unroll
        for (int mi = 0; mi < 2; mi++) {
            int r = m0 + wm * 32 + mi * 16 + g;
            float* c0 = accR[mi][ni];
            float* c1 = accI[mi][ni];
            float2 o0 = make_float2(c0[0] + br0, c0[1] + br1);
            float2 o1 = make_float2(c0[2] + br0, c0[3] + br1);
            float2 o2 = make_float2(c1[0] + bi0, c1[1] + bi1);
            float2 o3 = make_float2(c1[2] + bi0, c1[3] + bi1);
            size_t i0 = (size_t)r * N + n;
            size_t i1 = (size_t)(r + 8) * N + n;
            if (mode == 1) {
                float2 x0 = *(const float2*)&Xr[i0], x1 = *(const float2*)&Xr[i1];
                float2 y0 = *(const float2*)&Xi[i0], y1 = *(const float2*)&Xi[i1];
                o0.x += x0.x; o0.y += x0.y; o1.x += x1.x; o1.y += x1.y;
                o2.x += y0.x; o2.y += y0.y; o3.x += y1.x; o3.y += y1.y;
            } else if (mode == 3) {
                float2 x0 = *(const float2*)&Cr[i0], x1 = *(const float2*)&Cr[i1];
                float2 y0 = *(const float2*)&Ci[i0], y1 = *(const float2*)&Ci[i1];
                o0.x += x0.x; o0.y += x0.y; o1.x += x1.x; o1.y += x1.y;
                o2.x += y0.x; o2.y += y0.y; o3.x += y1.x; o3.y += y1.y;
            }
            *(float2*)&Cr[i0] = o0;
            *(float2*)&Cr[i1] = o1;
            *(float2*)&Ci[i0] = o2;
            *(float2*)&Ci[i1] = o3;
        }
    }
}

// RoPE cos/sin table: 1024 positions x 32 freqs, computed in double once.
__global__ __launch_bounds__(256) void rope_tab_kernel(float2* __restrict__ tab) {
    int idx = blockIdx.x * 256 + threadIdx.x;   // < 32768
    int j = idx & 31, s = idx >> 5;
    double invf = pow(10000.0, -(double)(2 * j) / 64.0);
    double ang = (double)s * invf;
    double sd, cd;
    sincos(ang, &sd, &cd);
    tab[idx] = make_float2((float)cd, (float)sd);
}

// RoPE in place on q,k (real & imag) using the table.
__global__ __launch_bounds__(256) void rope_kernel(float* __restrict__ qr, float* __restrict__ qi,
                                                   float* __restrict__ kr, float* __restrict__ ki,
                                                   const float2* __restrict__ tab) {
    int idx = blockIdx.x * 256 + threadIdx.x;   // < B*H*S*32 = 1048576
    int j = idx & 31;
    int s = (idx >> 5) & 1023;
    int h = (idx >> 15) & 7;
    int b = idx >> 18;
    float2 cspair = tab[idx & 32767];            // (s<<5)+j == idx & 32767
    float cs = cspair.x, sn = cspair.y;
    size_t base = (((size_t)b * SS + s) * DM) + h * HDD + j;
    float x0, x1;
    x0 = qr[base]; x1 = qr[base + 32]; qr[base] = x0 * cs - x1 * sn; qr[base + 32] = x1 * cs + x0 * sn;
    x0 = qi[base]; x1 = qi[base + 32]; qi[base] = x0 * cs - x1 * sn; qi[base + 32] = x1 * cs + x0 * sn;
    x0 = kr[base]; x1 = kr[base + 32]; kr[base] = x0 * cs - x1 * sn; kr[base + 32] = x1 * cs + x0 * sn;
    x0 = ki[base]; x1 = ki[base + 32]; ki[base] = x0 * cs - x1 * sn; ki[base + 32] = x1 * cs + x0 * sn;
}

// scores[bh, m, n] = (qr.kr + qi.ki)*scale ; only tiles with nt<=mt (causal)
__global__ __launch_bounds__(256) void scores_kernel(const float* __restrict__ qr,
                                                     const float* __restrict__ qi,
                                                     const float* __restrict__ kr,
                                                     const float* __restrict__ ki,
                                                     float* __restrict__ sc) {
    int bh = blockIdx.x, mt = blockIdx.y, nt = blockIdx.z;
    if (nt > mt) return;
    int b = bh >> 3, h = bh & 7;
    __shared__ float sQr[16][64], sQi[16][64], sKr[16][64], sKi[16][64];
    int m0 = mt * 64, n0 = nt * 64;
    int tx = threadIdx.x, ty = threadIdx.y;
    int tid = ty * 16 + tx;
    const size_t head_off = (size_t)b * SS * DM + (size_t)h * HDD;
    float acc[4][4] = {{0}};
    for (int k0 = 0; k0 < HDD; k0 += 16) {
        #pragma unroll
        for (int l = 0; l < 4; l++) {
            int idx = tid + l * 256;
            int r = idx >> 4, c = idx & 15;
            sQr[c][r] = qr[head_off + (size_t)(m0 + r) * DM + k0 + c];
            sQi[c][r] = qi[head_off + (size_t)(m0 + r) * DM + k0 + c];
            sKr[c][r] = kr[head_off + (size_t)(n0 + r) * DM + k0 + c];
            sKi[c][r] = ki[head_off + (size_t)(n0 + r) * DM + k0 + c];
        }
        __syncthreads();
        #pragma unroll
        for (int kk = 0; kk < 16; kk++) {
            float a[4], b2[4], c2[4], d2[4];
            #pragma unroll
            for (int j = 0; j < 4; j++) {
                a[j] = sQr[kk][ty * 4 + j];
                b2[j] = sQi[kk][ty * 4 + j];
                c2[j] = sKr[kk][tx * 4 + j];
                d2[j] = sKi[kk][tx * 4 + j];
            }
            #pragma unroll
            for (int i2 = 0; i2 < 4; i2++)
                #pragma unroll
                for (int j2 = 0; j2 < 4; j2++) {
                    acc[i2][j2] += a[i2] * c2[j2];
                    acc[i2][j2] += b2[i2] * d2[j2];
                }
        }
        __syncthreads();
    }
    const float scale = 0.125f;  // 1/sqrt(64)
    #pragma unroll
    for (int i2 = 0; i2 < 4; i2++) {
        size_t row = ((size_t)bh * SS + m0 + ty * 4 + i2) * SS;
        #pragma unroll
        for (int j2 = 0; j2 < 4; j2++)
            sc[row + n0 + tx * 4 + j2] = acc[i2][j2] * scale;
    }
}

// causal softmax per row; writes probs for col<=q, zeros for col>q
__global__ __launch_bounds__(256) void softmax_kernel(float* __restrict__ sc) {
    int row = blockIdx.x;          // bh*1024 + q
    int q = row & 1023;
    float* p = sc + (size_t)row * SS;
    int n = q + 1;
    int t = threadIdx.x;
    __shared__ float red[256];

    float mx = -1e30f;
    for (int i = t; i < n; i += 256) mx = fmaxf(mx, p[i]);
    red[t] = mx; __syncthreads();
    for (int s2 = 128; s2 > 0; s2 >>= 1) { if (t < s2) red[t] = fmaxf(red[t], red[t + s2]); __syncthreads(); }
    mx = red[0]; __syncthreads();

    float sum = 0.f;
    for (int i = t; i < n; i += 256) { float e = __expf(p[i] - mx); p[i] = e; sum += e; }
    red[t] = sum; __syncthreads();
    for (int s2 = 128; s2 > 0; s2 >>= 1) { if (t < s2) red[t] += red[t + s2]; __syncthreads(); }
    float inv = 1.0f / red[0];

    for (int i = t; i < n; i += 256) p[i] *= inv;
    for (int i = n + t; i < SS; i += 256) p[i] = 0.f;
}

// out[b, m, h*64+n] = sum_k attn[bh,m,k] * v[b,k,h*64+n]  (r and i), FFMA2
__global__ __launch_bounds__(256) void av_kernel(const float* __restrict__ attn,
                                                 const float* __restrict__ vr,
                                                 const float* __restrict__ vi,
                                                 float* __restrict__ ar_out,
                                                 float* __restrict__ ai_out) {
    int bh = blockIdx.x, mt = blockIdx.y;
    int b = bh >> 3, h = bh & 7;
    __shared__ float sP[16][64], sVr[16][64], sVi[16][64];
    int m0 = mt * 64;
    int tx = threadIdx.x, ty = threadIdx.y;
    int tid = ty * 16 + tx;
    ull accR[4][2], accI[4][2];
    #pragma unroll
    for (int i = 0; i < 4; i++) { accR[i][0] = accR[i][1] = 0ULL; accI[i][0] = accI[i][1] = 0ULL; }
    const size_t vbase = (size_t)b * SS * DM + (size_t)h * HDD;
    int kmax = m0 + 64;  // causal: tail zeros anyway
    for (int k0 = 0; k0 < kmax; k0 += 16) {
        #pragma unroll
        for (int l = 0; l < 4; l++) {
            int idx = tid + l * 256;
            int r = idx >> 4, c = idx & 15;
            sP[c][r] = attn[((size_t)bh * SS + m0 + r) * SS + k0 + c];
            int kk = idx >> 6, nn = idx & 63;
            sVr[kk][nn] = vr[vbase + (size_t)(k0 + kk) * DM + nn];
            sVi[kk][nn] = vi[vbase + (size_t)(k0 + kk) * DM + nn];
        }
        __syncthreads();
        #pragma unroll
        for (int kk = 0; kk < 16; kk++) {
            float4 pv = *(const float4*)&sP[kk][ty * 4];
            ulonglong2 vr2 = *(const ulonglong2*)&sVr[kk][tx * 4];
            ulonglong2 vi2 = *(const ulonglong2*)&sVi[kk][tx * 4];
            float ps[4] = {pv.x, pv.y, pv.z, pv.w};
            ull vrp[2] = {vr2.x, vr2.y};
            ull vip[2] = {vi2.x, vi2.y};
            #pragma unroll
            for (int i = 0; i < 4; i++) {
                ull pP = pk2(ps[i]);
                #pragma unroll
                for (int p = 0; p < 2; p++) {
                    fma2(accR[i][p], pP, vrp[p]);
                    fma2(accI[i][p], pP, vip[p]);
                }
            }
        }
        __syncthreads();
    }
    #pragma unroll
    for (int i = 0; i < 4; i++) {
        size_t orow = (size_t)b * SS * DM + (size_t)(m0 + ty * 4 + i) * DM + h * HDD + tx * 4;
        float2 r0 = up2(accR[i][0]), r1 = up2(accR[i][1]);
        float2 q0 = up2(accI[i][0]), q1 = up2(accI[i][1]);
        *(float4*)&ar_out[orow] = make_float4(r0.x, r0.y, r1.x, r1.y);
        *(float4*)&ai_out[orow] = make_float4(q0.x, q0.y, q1.x, q1.y);
    }
}

__global__ __launch_bounds__(256) void gateact_kernel(float* __restrict__ gr, float* __restrict__ gi,
                                                      const float* __restrict__ ur,
                                                      const float* __restrict__ ui) {
    size_t i = (size_t)blockIdx.x * 256 + threadIdx.x;
    float a = gr[i], b = gi[i];
    float mag = sqrtf(a * a + b * b);
    float s = 1.0f / (1.0f + expf(-mag));
    float gar = a * s, gai = b * s;
    float u = ur[i], v = ui[i];
    gr[i] = gar * u - gai * v;
    gi[i] = gar * v + gai * u;
}

// ---------------------------------------------------------------------------
extern "C" void kernel_launch(void* const* d_in, const int* in_sizes, int n_in,
                              void* d_out, int out_size) {
    const float* x_real = (const float*)d_in[0];
    const float* x_imag = (const float*)d_in[1];
    const float* ln1_gr = (const float*)d_in[2];
    const float* ln1_gi = (const float*)d_in[3];
    const float* ln1_br = (const float*)d_in[4];
    const float* ln1_bi = (const float*)d_in[5];
    const float* q_lm = (const float*)d_in[6];
    const float* q_ph = (const float*)d_in[7];
    const float* q_bm = (const float*)d_in[8];
    const float* q_bp = (const float*)d_in[9];
    const float* k_lm = (const float*)d_in[10];
    const float* k_ph = (const float*)d_in[11];
    const float* k_bm = (const float*)d_in[12];
    const float* k_bp = (const float*)d_in[13];
    const float* v_lm = (const float*)d_in[14];
    const float* v_ph = (const float*)d_in[15];
    const float* v_bm = (const float*)d_in[16];
    const float* v_bp = (const float*)d_in[17];
    const float* o_lm = (const float*)d_in[18];
    const float* o_ph = (const float*)d_in[19];
    const float* o_bm = (const float*)d_in[20];
    const float* o_bp = (const float*)d_in[21];
    const float* ln2_gr = (const float*)d_in[22];
    const float* ln2_gi = (const float*)d_in[23];
    const float* ln2_br = (const float*)d_in[24];
    const float* ln2_bi = (const float*)d_in[25];
    const float* gate_lm = (const float*)d_in[26];
    const float* gate_ph = (const float*)d_in[27];
    const float* up_lm = (const float*)d_in[28];
    const float* up_ph = (const float*)d_in[29];
    const float* down_lm = (const float*)d_in[30];
    const float* down_ph = (const float*)d_in[31];
    float* out = (float*)d_out;

    float* Sp = nullptr;
    cudaGetSymbolAddress((void**)&Sp, g_scratch);

    // scratch layout
    float* qwr = Sp;            // + q/k/v/o wr|wi pairs (8*DDE total)
    float* owr = Sp + 6 * DDE;  float* owi = owr + DDE;
    float* gwr = Sp + 8 * DDE;  // + gate/up/down wr|wi pairs (6*GDE)
    float* dwr = gwr + 4 * GDE; float* dwi = dwr + GDE;
    float* hr = gwr + 6 * GDE;  float* hi = hr + NDE;
    float* qr = hi + NDE;       float* qi = qr + NDE;
    float* kr = qi + NDE;       float* ki = kr + NDE;
    float* vr = ki + NDE;       float* vi = vr + NDE;
    float* ar = vi + NDE;       float* ai = ar + NDE;
    float* gr = ai + NDE;       float* gi = gr + NHE;
    float* ur = gi + NHE;       float* ui = ur + NHE;
    float* sc = ui + NHE;

    dim3 blk2(16, 16);

    // 1) materialize all weights in one launch
    make_w_all_kernel<<<(int)((4 * DDE + 3 * GDE) / 256), 256>>>(Sp,
        q_lm, q_ph, k_lm, k_ph, v_lm, v_ph, o_lm, o_ph,
        gate_lm, gate_ph, up_lm, up_ph, down_lm, down_ph);

    // 2) LN1
    cln_kernel<<<NT, 256>>>(x_real, x_imag, ln1_gr, ln1_gi, ln1_br, ln1_bi, hr, hi);

    // 3) QKV projections — ONE batched launch (z selects weight/output/bias)
    cgemm_tc_kernel<<<dim3(DM / 64, NT / 128, 3), 256>>>(
        hr, hi, qwr, 2 * DDE, DDE, qr, 2 * NDE, NDE,
        q_bm, q_bp, k_bm, k_bp, v_bm, v_bp, nullptr, nullptr, 0, NT, DM, DM);

    // 4) RoPE (table + apply)
    rope_tab_kernel<<<128, 256>>>((float2*)sc);
    rope_kernel<<<(BB * HH * SS * (HDD / 2)) / 256, 256>>>(qr, qi, kr, ki, (const float2*)sc);

    // 5) attention (exact fp32 FFMA2)
    scores_kernel<<<dim3(BB * HH, SS / 64, SS / 64), blk2>>>(qr, qi, kr, ki, sc);
    softmax_kernel<<<BB * HH * SS, 256>>>(sc);
    av_kernel<<<dim3(BB * HH, SS / 64), blk2>>>(sc, vr, vi, ar, ai);

    // 6) output projection with fused residual -> d_out directly (mode 1)
    cgemm_tc_kernel<<<dim3(DM / 64, NT / 128, 1), 256>>>(
        ar, ai, owr, 0, DDE, out, 0, NDE,
        o_bm, o_bp, nullptr, nullptr, nullptr, nullptr, x_real, x_imag, 1, NT, DM, DM);

    // 7) LN2 (reads residual from d_out)
    cln_kernel<<<NT, 256>>>(out, out + NDE, ln2_gr, ln2_gi, ln2_br, ln2_bi, hr, hi);

    // 8) FFN gate+up — ONE batched launch
    cgemm_tc_kernel<<<dim3(HIDD / 64, NT / 128, 2), 256>>>(
        hr, hi, gwr, 2 * GDE, GDE, gr, 2 * NHE, NHE,
        nullptr, nullptr, nullptr, nullptr, nullptr, nullptr, nullptr, nullptr, 0, NT, HIDD, DM);
    gateact_kernel<<<(int)(NHE / 256), 256>>>(gr, gi, ur, ui);

    // 9) down proj with fused accumulate into d_out (mode 3)
    cgemm_tc_kernel<<<dim3(DM / 64, NT / 128, 1), 256>>>(
        gr, gi, dwr, 0, GDE, out, 0, NDE,
        nullptr, nullptr, nullptr, nullptr, nullptr, nullptr, nullptr, nullptr, 3, NT, DM, HIDD);
}